// round 2
// baseline (speedup 1.0000x reference)
#include <cuda_runtime.h>
#include <math.h>

// ---------------------------------------------------------------------------
// Scratch (device globals -- no runtime allocation allowed)
// ---------------------------------------------------------------------------
__device__ float g_bufA[1024u * 256u * 256u];   // 256 MB: h1 / h3 / r1 / r3
__device__ float g_bufB[512u * 256u * 256u];    // 128 MB: h2 / r2
__device__ float g_field[2 * 256 * 256];        // refinement field
__device__ float g_bin[128 * 128];              // thresholded classification

#define KC 8   // input-channel chunk per smem stage

// ---------------------------------------------------------------------------
// 3x3 SAME conv, NCHW, implicit GEMM.
// Block = 256 threads, computes 64 Cout x 64 pixels (one 64-wide row segment).
// Thread micro-tile: 4 co x 4 px.  K loop chunks 8 input channels at a time.
// Weight smem is k-major ([ci][k][co]) so compute-phase weight reads are
// float4 (FMA:LDS inst ratio ~144:15 per channel -> FMA-pipe bound).
// ---------------------------------------------------------------------------
__global__ __launch_bounds__(256) void conv3x3_kernel(
    const float* __restrict__ in, const float* __restrict__ wgt,
    const float* __restrict__ bias, float* __restrict__ out,
    int Cin, int Cout, int H, int W, int doRelu)
{
    __shared__ __align__(16) float sIn[KC][3][68];  // 66 cols used (64 + halo)
    __shared__ __align__(16) float sW[KC][9][68];   // co padded 64->68 (banks)

    const int xtiles = W >> 6;                       // 2 or 4 (power of 2)
    const int tileX  = (blockIdx.x & (xtiles - 1)) << 6;
    const int y      = blockIdx.x / xtiles;
    const int coTile = blockIdx.y << 6;

    const int tid  = threadIdx.x;
    const int co0  = (tid >> 4) << 2;   // 0..60
    const int px0  = (tid & 15) << 2;   // 0..60
    const int warp = tid >> 5;
    const int lane = tid & 31;

    float acc[4][4];
#pragma unroll
    for (int i = 0; i < 4; i++)
#pragma unroll
        for (int j = 0; j < 4; j++) acc[i][j] = 0.f;

    for (int ci0 = 0; ci0 < Cin; ci0 += KC) {
        __syncthreads();
        // ---- load input halo tile: KC channels x 3 rows x 66 cols ----
        for (int r = warp; r < KC * 3; r += 8) {
            int ci = r / 3;
            int ky = r - ci * 3;
            int gy = y + ky - 1;
            bool yok = ((unsigned)gy < (unsigned)H);
            for (int j = lane; j < 66; j += 32) {
                int gx = tileX - 1 + j;
                float v = 0.f;
                if (yok && (unsigned)gx < (unsigned)W)
                    v = in[((ci0 + ci) * H + gy) * W + gx];
                sIn[ci][ky][j] = v;
            }
        }
        // ---- load weights: 64 co x KC ci x 9, store k-major ----
        for (int idx = tid; idx < 64 * KC * 9; idx += 256) {
            int co  = idx / (KC * 9);
            int rem = idx - co * (KC * 9);
            int ci  = rem / 9;
            int k   = rem - ci * 9;
            sW[ci][k][co] = wgt[((coTile + co) * Cin + (ci0 + ci)) * 9 + k];
        }
        __syncthreads();

        // ---- compute ----
#pragma unroll
        for (int ci = 0; ci < KC; ci++) {
            float4 wr[9];
#pragma unroll
            for (int k = 0; k < 9; k++)
                wr[k] = *(const float4*)&sW[ci][k][co0];
#pragma unroll
            for (int ky = 0; ky < 3; ky++) {
                float4 a  = *(const float4*)&sIn[ci][ky][px0];
                float2 b2 = *(const float2*)&sIn[ci][ky][px0 + 4];
                float xin[6] = {a.x, a.y, a.z, a.w, b2.x, b2.y};
#pragma unroll
                for (int kx = 0; kx < 3; kx++) {
                    float4 wv = wr[ky * 3 + kx];
#pragma unroll
                    for (int p = 0; p < 4; p++) {
                        float iv = xin[p + kx];
                        acc[0][p] = fmaf(wv.x, iv, acc[0][p]);
                        acc[1][p] = fmaf(wv.y, iv, acc[1][p]);
                        acc[2][p] = fmaf(wv.z, iv, acc[2][p]);
                        acc[3][p] = fmaf(wv.w, iv, acc[3][p]);
                    }
                }
            }
        }
    }

    // ---- epilogue ----
#pragma unroll
    for (int c = 0; c < 4; c++) {
        int co = coTile + co0 + c;
        float bv = bias[co];
        float* dst = out + (co * H + y) * W + tileX + px0;
#pragma unroll
        for (int p = 0; p < 4; p++) {
            float v = acc[c][p] + bv;
            if (doRelu) v = fmaxf(v, 0.f);
            dst[p] = v;
        }
    }
}

// ---------------------------------------------------------------------------
// 1x1 conv 256->1 + sigmoid + threshold (classification head)
// ---------------------------------------------------------------------------
__global__ void cls_kernel(const float* __restrict__ h, const float* __restrict__ w,
                           const float* __restrict__ b, float* __restrict__ cls,
                           float* __restrict__ bin, int HW)
{
    int p = blockIdx.x * 256 + threadIdx.x;
    if (p >= HW) return;
    float s = b[0];
#pragma unroll 8
    for (int c = 0; c < 256; c++) s = fmaf(w[c], h[c * HW + p], s);
    float sig = 1.f / (1.f + expf(-s));
    cls[p] = sig;
    bin[p] = (sig >= 0.5f) ? 1.f : 0.f;
}

// ---------------------------------------------------------------------------
// 1x1 conv 256->2 (refinement field head)
// ---------------------------------------------------------------------------
__global__ void field_kernel(const float* __restrict__ r, const float* __restrict__ w,
                             const float* __restrict__ b, float* __restrict__ field,
                             int HW)
{
    int p = blockIdx.x * 256 + threadIdx.x;
    if (p >= HW) return;
    float s0 = b[0], s1 = b[1];
#pragma unroll 8
    for (int c = 0; c < 256; c++) {
        float v = r[c * HW + p];
        s0 = fmaf(w[c], v, s0);
        s1 = fmaf(w[256 + c], v, s1);
    }
    field[p] = s0;
    field[HW + p] = s1;
}

// ---------------------------------------------------------------------------
// 2x bilinear upsample (align-corners linspace) of binary map + round-half-even
// ---------------------------------------------------------------------------
__global__ void upsample_kernel(const float* __restrict__ bin, float* __restrict__ out)
{
    int idx = blockIdx.x * 256 + threadIdx.x;
    if (idx >= 256 * 256) return;
    int Y = idx >> 8, X = idx & 255;
    const float step = 127.0f / 255.0f;   // linspace(0,127,256) delta, fp32
    float ys = (float)Y * step;
    float xs = (float)X * step;
    int y0 = (int)floorf(ys); int y1 = min(y0 + 1, 127);
    int x0 = (int)floorf(xs); int x1 = min(x0 + 1, 127);
    float wy = ys - (float)y0;
    float wx = xs - (float)x0;
    float v00 = bin[y0 * 128 + x0], v01 = bin[y0 * 128 + x1];
    float v10 = bin[y1 * 128 + x0], v11 = bin[y1 * 128 + x1];
    float val = (v00 * (1.f - wx) + v01 * wx) * (1.f - wy)
              + (v10 * (1.f - wx) + v11 * wx) * wy;
    out[idx] = rintf(val);   // round-half-even == jnp.round
}

// ---------------------------------------------------------------------------
// Iterative contour refinement.  num_iter is a DEVICE scalar -> loop on device
// (graph-capture safe, no host readback).  Points are independent.
// ---------------------------------------------------------------------------
__global__ void contour_kernel(const float* __restrict__ cc,
                               const float* __restrict__ field,
                               const int* __restrict__ pnum_iter,
                               float* __restrict__ out, int npts)
{
    int i = blockIdx.x * 256 + threadIdx.x;
    if (i >= npts) return;
    const int W = 256, H = 256;
    float x = cc[2 * i];
    float y = cc[2 * i + 1];
    int n = pnum_iter[0];
    for (int t = 0; t < n; t++) {
        float xc = fminf(fmaxf(x, 0.f), (float)(W - 1));
        float yc = fminf(fmaxf(y, 0.f), (float)(H - 1));
        int x0 = (int)floorf(xc); int x1 = min(x0 + 1, W - 1);
        int y0 = (int)floorf(yc); int y1 = min(y0 + 1, H - 1);
        float wx = xc - (float)x0;
        float wy = yc - (float)y0;
        float ox, oy;
        {
            const float* f = field;  // channel 0 -> x offset
            float v00 = f[y0 * W + x0], v01 = f[y0 * W + x1];
            float v10 = f[y1 * W + x0], v11 = f[y1 * W + x1];
            ox = (v00 * (1.f - wx) + v01 * wx) * (1.f - wy)
               + (v10 * (1.f - wx) + v11 * wx) * wy;
        }
        {
            const float* f = field + H * W;  // channel 1 -> y offset
            float v00 = f[y0 * W + x0], v01 = f[y0 * W + x1];
            float v10 = f[y1 * W + x0], v11 = f[y1 * W + x1];
            oy = (v00 * (1.f - wx) + v01 * wx) * (1.f - wy)
               + (v10 * (1.f - wx) + v11 * wx) * wy;
        }
        x = fminf(fmaxf(x + ox, 0.f), (float)(W - 1));
        y = fminf(fmaxf(y + oy, 0.f), (float)(H - 1));
    }
    out[2 * i]     = x;
    out[2 * i + 1] = y;
}

// ---------------------------------------------------------------------------
// Launch
// ---------------------------------------------------------------------------
extern "C" void kernel_launch(void* const* d_in, const int* in_sizes, int n_in,
                              void* d_out, int out_size)
{
    const float* f1  = (const float*)d_in[0];   // (1,512,256,256)
    const float* f2  = (const float*)d_in[1];   // (1,512,128,128)
    const float* cc  = (const float*)d_in[2];   // (1,600,64,2)
    const float* cw1 = (const float*)d_in[3];
    const float* cb1 = (const float*)d_in[4];
    const float* cw2 = (const float*)d_in[5];
    const float* cb2 = (const float*)d_in[6];
    const float* cw3 = (const float*)d_in[7];
    const float* cb3 = (const float*)d_in[8];
    const float* cw4 = (const float*)d_in[9];
    const float* cb4 = (const float*)d_in[10];
    const float* rw1 = (const float*)d_in[11];
    const float* rb1 = (const float*)d_in[12];
    const float* rw2 = (const float*)d_in[13];
    const float* rb2 = (const float*)d_in[14];
    const float* rw3 = (const float*)d_in[15];
    const float* rb3 = (const float*)d_in[16];
    const float* rw4 = (const float*)d_in[17];
    const float* rb4 = (const float*)d_in[18];
    const int* pnum  = (const int*)d_in[19];

    float* out = (float*)d_out;
    float* out_cls = out;                    // 16384
    float* out_bin = out + 16384;            // 65536
    float* out_ctr = out + 16384 + 65536;    // 76800

    float *bufA, *bufB, *field, *bin;
    cudaGetSymbolAddress((void**)&bufA,  g_bufA);
    cudaGetSymbolAddress((void**)&bufB,  g_bufB);
    cudaGetSymbolAddress((void**)&field, g_field);
    cudaGetSymbolAddress((void**)&bin,   g_bin);

    // ---- classification branch (128x128) ----
    {
        dim3 g1((128 / 64) * 128, 1024 / 64);
        conv3x3_kernel<<<g1, 256>>>(f2,   cw1, cb1, bufA, 512, 1024, 128, 128, 1);
        dim3 g2((128 / 64) * 128, 512 / 64);
        conv3x3_kernel<<<g2, 256>>>(bufA, cw2, cb2, bufB, 1024, 512, 128, 128, 1);
        dim3 g3((128 / 64) * 128, 256 / 64);
        conv3x3_kernel<<<g3, 256>>>(bufB, cw3, cb3, bufA, 512, 256, 128, 128, 1);
        cls_kernel<<<(16384 + 255) / 256, 256>>>(bufA, cw4, cb4, out_cls, bin, 16384);
        upsample_kernel<<<(65536 + 255) / 256, 256>>>(bin, out_bin);
    }

    // ---- refinement branch (256x256) ----
    {
        dim3 g1((256 / 64) * 256, 1024 / 64);
        conv3x3_kernel<<<g1, 256>>>(f1,   rw1, rb1, bufA, 512, 1024, 256, 256, 1);
        dim3 g2((256 / 64) * 256, 512 / 64);
        conv3x3_kernel<<<g2, 256>>>(bufA, rw2, rb2, bufB, 1024, 512, 256, 256, 1);
        dim3 g3((256 / 64) * 256, 256 / 64);
        conv3x3_kernel<<<g3, 256>>>(bufB, rw3, rb3, bufA, 512, 256, 256, 256, 1);
        field_kernel<<<(65536 + 255) / 256, 256>>>(bufA, rw4, rb4, field, 65536);
        contour_kernel<<<(38400 + 255) / 256, 256>>>(cc, field, pnum, out_ctr, 38400);
    }
}